// round 3
// baseline (speedup 1.0000x reference)
#include <cuda_runtime.h>
#include <cstdint>

// ---------------- problem shapes ----------------
#define T_TOK 2048   // S*B tokens
#define HID   1024   // H
#define FF    4096   // F
#define NE    4      // experts

// ---------------- tiling ----------------
#define MT 128
#define NT 256
#define KTILE 32
#define NS 4                      // pipeline buffers (3 in flight)
#define STAGEF 13056              // floats per stage: A 128*36=4608 + B 32*264=8448
#define AOFF 0
#define BOFF 4608
#define SMEM_DYN (NS * STAGEF * 4)   // 208896 B

// ---------------- device scratch (allocation-guard-safe) ----------------
__device__ int   g_cnt[NE];
__device__ int   g_idx[NE * T_TOK];
__device__ float g_gate[NE * T_TOK];
__device__ int   g_src[T_TOK * 2];                       // token -> (e*T_TOK+pos) x2
__device__ float g_act[(size_t)NE * T_TOK * FF];         // fc1 output (gelu'd)
__device__ float g_y[(size_t)2 * NE * T_TOK * HID];      // fc2 partials (2 k-splits)

// ---------------- helpers ----------------
__device__ __forceinline__ uint32_t smem_u32(const void* p) {
    uint32_t a;
    asm("{ .reg .u64 t; cvta.to.shared.u64 t, %1; cvt.u32.u64 %0, t; }" : "=r"(a) : "l"(p));
    return a;
}
__device__ __forceinline__ uint32_t f2tf(float x) {
    uint32_t u;
    asm("cvt.rna.tf32.f32 %0, %1;" : "=r"(u) : "f"(x));
    return u;
}
__device__ __forceinline__ void mma_tf32(float* d, const uint32_t* a, const uint32_t* b) {
    asm volatile(
        "mma.sync.aligned.m16n8k8.row.col.f32.tf32.tf32.f32 "
        "{%0,%1,%2,%3}, {%4,%5,%6,%7}, {%8,%9}, {%0,%1,%2,%3};\n"
        : "+f"(d[0]), "+f"(d[1]), "+f"(d[2]), "+f"(d[3])
        : "r"(a[0]), "r"(a[1]), "r"(a[2]), "r"(a[3]), "r"(b[0]), "r"(b[1]));
}
__device__ __forceinline__ void cp_async16(uint32_t dst, const float* src) {
    asm volatile("cp.async.cg.shared.global [%0], [%1], 16;\n" :: "r"(dst), "l"(src));
}
__device__ __forceinline__ float tf32_rna_f(float x) {
    uint32_t u;
    asm("cvt.rna.tf32.f32 %0, %1;" : "=r"(u) : "f"(x));
    return __uint_as_float(u);
}
__device__ __forceinline__ float gelu_exact(float v) {
    return 0.5f * v * (1.0f + erff(v * 0.70710678118654752f));
}

// ---------------- kernel 1: zero counters / src map ----------------
__global__ void init_kernel() {
    int i = blockIdx.x * blockDim.x + threadIdx.x;
    if (i < T_TOK * 2) g_src[i] = -1;
    if (i < NE) g_cnt[i] = 0;
}

// ---------------- kernel 2: routing lists ----------------
__global__ void route_kernel(const float* __restrict__ probs) {
    int t = blockIdx.x * blockDim.x + threadIdx.x;
    if (t >= T_TOK) return;
    int nl = 0;
    #pragma unroll
    for (int e = 0; e < NE; e++) {
        float p = probs[t * NE + e];
        if (p > 0.f) {
            int pos = atomicAdd(&g_cnt[e], 1);
            g_idx[e * T_TOK + pos]  = t;
            g_gate[e * T_TOK + pos] = p;
            if (nl < 2) g_src[t * 2 + nl] = e * T_TOK + pos;
            nl++;
        }
    }
}

// ---------------- stage fill ----------------
template <int MODE>
__device__ __forceinline__ void fill_stage(uint32_t sbase,   // byte addr of stage
                                           const float* __restrict__ X,
                                           const float* __restrict__ W,
                                           const int* s_tok, int e, int m0, int n0,
                                           int k0, int tid) {
    constexpr int LDB = MODE ? HID : FF;
    // A: 128 rows x 32 floats (pad to 36)
    #pragma unroll
    for (int p = 0; p < 4; p++) {
        int idx = p * 256 + tid;
        int row = idx >> 3, c = idx & 7;
        const float* src = (MODE == 0)
            ? X + (size_t)s_tok[row] * HID + k0 + c * 4
            : g_act + ((size_t)e * T_TOK + m0 + row) * FF + k0 + c * 4;
        cp_async16(sbase + (uint32_t)(AOFF + row * 36 + c * 4) * 4, src);
    }
    // B: 32 rows x 256 floats (pad to 264)
    #pragma unroll
    for (int p = 0; p < 8; p++) {
        int idx = p * 256 + tid;
        int row = idx >> 6, c4 = idx & 63;
        const float* src = W + (size_t)(k0 + row) * LDB + n0 + c4 * 4;
        cp_async16(sbase + (uint32_t)(BOFF + row * 264 + c4 * 4) * 4, src);
    }
    asm volatile("cp.async.commit_group;\n" ::: "memory");
}

// ---------------- grouped GEMM ----------------
// MODE 0: fc1  A = x[gather] (K=HID), B = w1[e], epi: gelu -> g_act
// MODE 1: fc2  A = g_act (K=FF/2 per split), B = w2[e], epi: gate * val -> g_y[split]
template <int MODE>
__global__ __launch_bounds__(256, 1)
void moe_gemm(const float* __restrict__ X, const float* __restrict__ W0) {
    constexpr int K  = MODE ? (FF / 2) : HID;
    constexpr int KT = K / KTILE;

    const int e  = MODE ? (blockIdx.z >> 1) : blockIdx.z;
    const int ks = MODE ? (blockIdx.z & 1) : 0;
    const int m0 = blockIdx.y * MT;
    const int n0 = blockIdx.x * NT;
    const int cnt = g_cnt[e];
    if (m0 >= cnt) return;
    const int kbase = MODE ? ks * (FF / 2) : 0;
    const float* W = W0 + (size_t)e * HID * FF;

    extern __shared__ float sm[];
    const uint32_t sb = smem_u32(sm);
    __shared__ int   s_tok[128];
    __shared__ float s_gate[128];

    const int tid = threadIdx.x, w = tid >> 5, lane = tid & 31;
    const int g = lane >> 2, tg = lane & 3;
    const int wm = (w & 1) * 64;
    const int wn = (w >> 1) * 64;

    if (tid < 128) {
        int m = m0 + tid;
        bool v = m < cnt;
        s_tok[tid]  = v ? g_idx[e * T_TOK + m] : 0;
        s_gate[tid] = (MODE && v) ? g_gate[e * T_TOK + m] : 0.f;
    }
    __syncthreads();

    // prologue: 3 tiles in flight
    #pragma unroll
    for (int s = 0; s < 3; s++)
        fill_stage<MODE>(sb + s * STAGEF * 4, X, W, s_tok, e, m0, n0,
                         kbase + s * KTILE, tid);

    float acc[4][8][4];
    #pragma unroll
    for (int i = 0; i < 4; i++)
        #pragma unroll
        for (int jj = 0; jj < 8; jj++)
            #pragma unroll
            for (int q = 0; q < 4; q++) acc[i][jj][q] = 0.f;

    for (int j = 0; j < KT; ++j) {
        asm volatile("cp.async.wait_group %0;\n" :: "n"(2) : "memory");
        __syncthreads();
        if (j + 3 < KT)
            fill_stage<MODE>(sb + ((j + 3) & 3) * STAGEF * 4, X, W, s_tok, e, m0, n0,
                             kbase + (j + 3) * KTILE, tid);
        else
            asm volatile("cp.async.commit_group;\n" ::: "memory");

        const int stf = (j & 3) * STAGEF;
        #pragma unroll
        for (int kk = 0; kk < 4; kk++) {
            const int k = kk * 8;
            uint32_t a[4][4], b[8][2];
            #pragma unroll
            for (int mf = 0; mf < 4; mf++) {
                const int r = wm + mf * 16 + g;
                a[mf][0] = f2tf(sm[stf + r * 36 + k + tg]);
                a[mf][1] = f2tf(sm[stf + (r + 8) * 36 + k + tg]);
                a[mf][2] = f2tf(sm[stf + r * 36 + k + tg + 4]);
                a[mf][3] = f2tf(sm[stf + (r + 8) * 36 + k + tg + 4]);
            }
            #pragma unroll
            for (int nf = 0; nf < 8; nf++) {
                const int c = wn + nf * 8 + g;
                b[nf][0] = f2tf(sm[stf + BOFF + (k + tg) * 264 + c]);
                b[nf][1] = f2tf(sm[stf + BOFF + (k + tg + 4) * 264 + c]);
            }
            #pragma unroll
            for (int mf = 0; mf < 4; mf++)
                #pragma unroll
                for (int nf = 0; nf < 8; nf++)
                    mma_tf32(acc[mf][nf], a[mf], b[nf]);
        }
    }

    // epilogue
    #pragma unroll
    for (int mf = 0; mf < 4; mf++) {
        #pragma unroll
        for (int i2 = 0; i2 < 2; i2++) {
            const int r = wm + mf * 16 + g + i2 * 8;
            const int grow = m0 + r;
            if (grow < cnt) {
                if (MODE == 0) {
                    float* dst = g_act + ((size_t)e * T_TOK + grow) * FF + n0 + wn;
                    #pragma unroll
                    for (int nf = 0; nf < 8; nf++) {
                        float v0 = acc[mf][nf][i2 * 2 + 0];
                        float v1 = acc[mf][nf][i2 * 2 + 1];
                        float2 o = make_float2(tf32_rna_f(gelu_exact(v0)),
                                               tf32_rna_f(gelu_exact(v1)));
                        *reinterpret_cast<float2*>(dst + nf * 8 + tg * 2) = o;
                    }
                } else {
                    const float gt = s_gate[r];
                    float* dst = g_y + (((size_t)ks * NE + e) * T_TOK + grow) * HID + n0 + wn;
                    #pragma unroll
                    for (int nf = 0; nf < 8; nf++) {
                        float2 o = make_float2(gt * acc[mf][nf][i2 * 2 + 0],
                                               gt * acc[mf][nf][i2 * 2 + 1]);
                        *reinterpret_cast<float2*>(dst + nf * 8 + tg * 2) = o;
                    }
                }
            }
        }
    }
}

// ---------------- combine: out = residual + sum of gated expert outputs ----------------
__global__ void combine_kernel(const float* __restrict__ res, float* __restrict__ out) {
    const int t  = blockIdx.x;
    const int h4 = threadIdx.x;                       // 256 float4 per token
    const size_t o = (size_t)t * 256 + h4;
    float4 accv = reinterpret_cast<const float4*>(res)[o];
    #pragma unroll
    for (int slot = 0; slot < 2; slot++) {
        int sidx = g_src[t * 2 + slot];
        if (sidx >= 0) {
            const float4* y0 = reinterpret_cast<const float4*>(g_y) + (size_t)sidx * 256 + h4;
            const float4* y1 = reinterpret_cast<const float4*>(g_y)
                               + ((size_t)NE * T_TOK + sidx) * 256 + h4;
            float4 a0 = *y0, a1 = *y1;
            accv.x += a0.x + a1.x;
            accv.y += a0.y + a1.y;
            accv.z += a0.z + a1.z;
            accv.w += a0.w + a1.w;
        }
    }
    reinterpret_cast<float4*>(out)[o] = accv;
}

// ---------------- launch ----------------
extern "C" void kernel_launch(void* const* d_in, const int* in_sizes, int n_in,
                              void* d_out, int out_size) {
    const float* hs    = (const float*)d_in[0];
    const float* res   = (const float*)d_in[1];
    const float* probs = (const float*)d_in[2];
    const float* w1    = (const float*)d_in[4];
    const float* w2    = (const float*)d_in[5];
    float* out = (float*)d_out;

    cudaFuncSetAttribute(moe_gemm<0>, cudaFuncAttributeMaxDynamicSharedMemorySize, SMEM_DYN);
    cudaFuncSetAttribute(moe_gemm<1>, cudaFuncAttributeMaxDynamicSharedMemorySize, SMEM_DYN);

    init_kernel<<<16, 256>>>();
    route_kernel<<<(T_TOK + 255) / 256, 256>>>(probs);
    // fc1: 16 N-tiles x 16 M-tiles x 4 experts
    moe_gemm<0><<<dim3(FF / NT, T_TOK / MT, NE), 256, SMEM_DYN>>>(hs, w1);
    // fc2: 4 N-tiles x 16 M-tiles x (4 experts * 2 k-splits)
    moe_gemm<1><<<dim3(HID / NT, T_TOK / MT, NE * 2), 256, SMEM_DYN>>>(nullptr, w2);
    combine_kernel<<<T_TOK, 256>>>(res, out);
}